// round 9
// baseline (speedup 1.0000x reference)
#include <cuda_runtime.h>
#include <cstdint>

// GwcVolume: B=1, F=320, H=128, W=256, G=40, C=8; D = in_sizes[2] (bins = arange(D))
#define W_DIM 256
#define H_DIM 128
#define G_DIM 40
#define C_DIM 8
#define PAD   48                 // max disparity padding (zeros)
#define SLOTS (W_DIM + PAD)      // 304 slots, 32B each (8 channels fp32)

// 128B XOR swizzle
__device__ __forceinline__ int swz(int off) {
    return off ^ ((off >> 3) & 0x70);
}

__device__ __forceinline__ float dot8(float4 la, float4 lb, float4 ra, float4 rb) {
    float s = la.x * ra.x;
    s = fmaf(la.y, ra.y, s);
    s = fmaf(la.z, ra.z, s);
    s = fmaf(la.w, ra.w, s);
    s = fmaf(lb.x, rb.x, s);
    s = fmaf(lb.y, rb.y, s);
    s = fmaf(lb.z, rb.z, s);
    s = fmaf(lb.w, rb.w, s);
    return s;
}

__global__ __launch_bounds__(256, 4)
void gwc_kernel(const float* __restrict__ L,
                const float* __restrict__ R,
                const int* __restrict__ bins,
                int D,
                float* __restrict__ out)
{
    __shared__ __align__(128) char l_raw[SLOTS * 32];  // slot p = left pos p   (zeros p>=256)
    __shared__ __align__(128) char r_raw[SLOTS * 32];  // slot p = right pos p-PAD (zeros p<PAD)
    __shared__ int d0_s;

    const int tid = threadIdx.x;
    const int h = blockIdx.x;
    const int g = blockIdx.y;

    if (tid == 0) d0_s = bins[0];

    const size_t plane = (size_t)H_DIM * W_DIM;
    const float* Lrow = L + (size_t)(g * C_DIM) * plane + (size_t)h * W_DIM;
    const float* Rrow = R + (size_t)(g * C_DIM) * plane + (size_t)h * W_DIM;

    // Populate left (transposed [w][c], swizzled), zero pad at top
    for (int p = tid; p < SLOTS; p += 256) {
        float v[8];
        if (p < W_DIM) {
#pragma unroll
            for (int c = 0; c < 8; c++) v[c] = Lrow[(size_t)c * plane + p];
        } else {
#pragma unroll
            for (int c = 0; c < 8; c++) v[c] = 0.0f;
        }
        *(float4*)(l_raw + swz(p * 32))      = make_float4(v[0], v[1], v[2], v[3]);
        *(float4*)(l_raw + swz(p * 32 + 16)) = make_float4(v[4], v[5], v[6], v[7]);
    }
    // Populate right, zero pad at bottom (PAD slots)
    for (int p = tid; p < SLOTS; p += 256) {
        float v[8];
        const int w = p - PAD;
        if (w >= 0) {
#pragma unroll
            for (int c = 0; c < 8; c++) v[c] = Rrow[(size_t)c * plane + w];
        } else {
#pragma unroll
            for (int c = 0; c < 8; c++) v[c] = 0.0f;
        }
        *(float4*)(r_raw + swz(p * 32))      = make_float4(v[0], v[1], v[2], v[3]);
        *(float4*)(r_raw + swz(p * 32 + 16)) = make_float4(v[4], v[5], v[6], v[7]);
    }
    __syncthreads();

    const int d0 = d0_s;
    const size_t VOL = (size_t)G_DIM * D * plane;
    float* __restrict__ lr = out;
    float* __restrict__ rl = out + VOL;

    if (tid < 128) {
        // ---- lr threads: fixed left pair (w0, w0+1), slide right window down ----
        const int w0 = tid * 2;
        float4 lA0 = *(const float4*)(l_raw + swz((w0 + 0) * 32));
        float4 lB0 = *(const float4*)(l_raw + swz((w0 + 0) * 32 + 16));
        float4 lA1 = *(const float4*)(l_raw + swz((w0 + 1) * 32));
        float4 lB1 = *(const float4*)(l_raw + swz((w0 + 1) * 32 + 16));

        // prologue: r position w0+1-d0 (slot = pos + PAD; always in [0, SLOTS))
        int sTop = w0 + 1 - d0 + PAD;
        float4 a1 = *(const float4*)(r_raw + swz(sTop * 32));
        float4 b1 = *(const float4*)(r_raw + swz(sTop * 32 + 16));

        float* plr = lr + (size_t)g * D * plane + (size_t)h * W_DIM + w0;
        int s = w0 - d0 + PAD;

#pragma unroll 4
        for (int i = 0; i < D; i++) {
            float4 a0 = *(const float4*)(r_raw + swz(s * 32));
            float4 b0 = *(const float4*)(r_raw + swz(s * 32 + 16));

            float c0 = dot8(lA0, lB0, a0, b0) * 0.125f;
            float c1 = dot8(lA1, lB1, a1, b1) * 0.125f;

            *(float2*)plr = make_float2(c0, c1);
            plr += plane;

            a1 = a0; b1 = b0;
            s -= 1;
        }
    } else {
        // ---- rl threads: fixed right pair (q0, q0+1), slide left window up ----
        const int q0 = (tid - 128) * 2;
        float4 rA0 = *(const float4*)(r_raw + swz((q0 + 0 + PAD) * 32));
        float4 rB0 = *(const float4*)(r_raw + swz((q0 + 0 + PAD) * 32 + 16));
        float4 rA1 = *(const float4*)(r_raw + swz((q0 + 1 + PAD) * 32));
        float4 rB1 = *(const float4*)(r_raw + swz((q0 + 1 + PAD) * 32 + 16));

        // prologue: left position q0+d0 (slot = pos; pads above 256 are zeros)
        int sBot = q0 + d0;
        float4 a0 = *(const float4*)(l_raw + swz(sBot * 32));
        float4 b0 = *(const float4*)(l_raw + swz(sBot * 32 + 16));

        float* prl = rl + (size_t)g * D * plane + (size_t)h * W_DIM + q0;
        int s = q0 + 1 + d0;

#pragma unroll 4
        for (int i = 0; i < D; i++) {
            float4 a1 = *(const float4*)(l_raw + swz(s * 32));
            float4 b1 = *(const float4*)(l_raw + swz(s * 32 + 16));

            // rl[q+k] = mean_c L[c, q+k+d] * R[c, q+k]
            float c0 = dot8(a0, b0, rA0, rB0) * 0.125f;
            float c1 = dot8(a1, b1, rA1, rB1) * 0.125f;

            *(float2*)prl = make_float2(c0, c1);
            prl += plane;

            a0 = a1; b0 = b1;
            s += 1;
        }
    }
}

extern "C" void kernel_launch(void* const* d_in, const int* in_sizes, int n_in,
                              void* d_out, int out_size) {
    const float* L    = (const float*)d_in[0];
    const float* R    = (const float*)d_in[1];
    const int*   bins = (const int*)d_in[2];
    const int D = in_sizes[2];   // 48

    dim3 grid(H_DIM, G_DIM);     // one block per (h, g)
    dim3 block(256);             // 128 lr-pair threads + 128 rl-pair threads
    gwc_kernel<<<grid, block>>>(L, R, bins, D, (float*)d_out);
}

// round 10
// speedup vs baseline: 1.1495x; 1.1495x over previous
#include <cuda_runtime.h>
#include <cstdint>

// GwcVolume: B=1, F=320, H=128, W=256, G=40, C=8; D = in_sizes[2] (bins = arange(D))
#define W_DIM 256
#define H_DIM 128
#define G_DIM 40
#define C_DIM 8
#define PAD   48                 // max disparity padding (zeros)
#define SLOTS (W_DIM + PAD)      // 304 slots, 32B each (8 channels fp32)

// 128B XOR swizzle
__device__ __forceinline__ int swz(int off) {
    return off ^ ((off >> 3) & 0x70);
}

__device__ __forceinline__ float dot8(float4 la, float4 lb, float4 ra, float4 rb) {
    float s = la.x * ra.x;
    s = fmaf(la.y, ra.y, s);
    s = fmaf(la.z, ra.z, s);
    s = fmaf(la.w, ra.w, s);
    s = fmaf(lb.x, rb.x, s);
    s = fmaf(lb.y, rb.y, s);
    s = fmaf(lb.z, rb.z, s);
    s = fmaf(lb.w, rb.w, s);
    return s * 0.125f;           // mean over C=8
}

__global__ __launch_bounds__(128, 8)
void gwc_kernel(const float* __restrict__ L,
                const float* __restrict__ R,
                const int* __restrict__ bins,
                int D,
                float* __restrict__ out)
{
    __shared__ __align__(128) char l_raw[SLOTS * 32];  // slot p = left pos p    (zeros p>=256)
    __shared__ __align__(128) char r_raw[SLOTS * 32];  // slot p = right pos p-PAD (zeros p<PAD)
    __shared__ int d0_s;

    const int tid = threadIdx.x;
    const int h = blockIdx.x;
    const int g = blockIdx.y;

    if (tid == 0) d0_s = bins[0];

    const size_t plane = (size_t)H_DIM * W_DIM;
    const float* Lrow = L + (size_t)(g * C_DIM) * plane + (size_t)h * W_DIM;
    const float* Rrow = R + (size_t)(g * C_DIM) * plane + (size_t)h * W_DIM;

    // Populate left (transposed [w][c], swizzled), zero pad at top
    for (int p = tid; p < SLOTS; p += 128) {
        float v[8];
        if (p < W_DIM) {
#pragma unroll
            for (int c = 0; c < 8; c++) v[c] = Lrow[(size_t)c * plane + p];
        } else {
#pragma unroll
            for (int c = 0; c < 8; c++) v[c] = 0.0f;
        }
        *(float4*)(l_raw + swz(p * 32))      = make_float4(v[0], v[1], v[2], v[3]);
        *(float4*)(l_raw + swz(p * 32 + 16)) = make_float4(v[4], v[5], v[6], v[7]);
    }
    // Populate right, zero pad at bottom (PAD slots)
    for (int p = tid; p < SLOTS; p += 128) {
        float v[8];
        const int w = p - PAD;
        if (w >= 0) {
#pragma unroll
            for (int c = 0; c < 8; c++) v[c] = Rrow[(size_t)c * plane + w];
        } else {
#pragma unroll
            for (int c = 0; c < 8; c++) v[c] = 0.0f;
        }
        *(float4*)(r_raw + swz(p * 32))      = make_float4(v[0], v[1], v[2], v[3]);
        *(float4*)(r_raw + swz(p * 32 + 16)) = make_float4(v[4], v[5], v[6], v[7]);
    }
    __syncthreads();

    const int d0 = d0_s;
    const size_t VOL = (size_t)G_DIM * D * plane;
    float* __restrict__ lr = out;
    float* __restrict__ rl = out + VOL;

    if (tid < 64) {
        // ---- lr: fixed left quad (w0..w0+3); one r load per iter serves k=0..3
        // lr[w0+k, d0+i] = dot(l_k, r[w0+k-d0-i]); load at iter j: r pos w0-d0-j
        // serves (k, i=j+k). Store row i: (c0(i), c1(i-1), c2(i-2), c3(i-3)).
        const int w0 = tid * 4;
        float4 lA0 = *(const float4*)(l_raw + swz((w0 + 0) * 32));
        float4 lB0 = *(const float4*)(l_raw + swz((w0 + 0) * 32 + 16));
        float4 lA1 = *(const float4*)(l_raw + swz((w0 + 1) * 32));
        float4 lB1 = *(const float4*)(l_raw + swz((w0 + 1) * 32 + 16));
        float4 lA2 = *(const float4*)(l_raw + swz((w0 + 2) * 32));
        float4 lB2 = *(const float4*)(l_raw + swz((w0 + 2) * 32 + 16));
        float4 lA3 = *(const float4*)(l_raw + swz((w0 + 3) * 32));
        float4 lB3 = *(const float4*)(l_raw + swz((w0 + 3) * 32 + 16));

        // Prologue: loads at j=-1,-2,-3 (slots w0-d0+PAD+1..3, all < SLOTS)
        float q1, q2_0, q2_1, q3_0, q3_1, q3_2;
        {
            int sl = w0 - d0 + PAD;
            float4 a, b;
            a = *(const float4*)(r_raw + swz((sl + 1) * 32));
            b = *(const float4*)(r_raw + swz((sl + 1) * 32 + 16));
            q1   = dot8(lA1, lB1, a, b);
            q2_1 = dot8(lA2, lB2, a, b);
            q3_2 = dot8(lA3, lB3, a, b);
            a = *(const float4*)(r_raw + swz((sl + 2) * 32));
            b = *(const float4*)(r_raw + swz((sl + 2) * 32 + 16));
            q2_0 = dot8(lA2, lB2, a, b);
            q3_1 = dot8(lA3, lB3, a, b);
            a = *(const float4*)(r_raw + swz((sl + 3) * 32));
            b = *(const float4*)(r_raw + swz((sl + 3) * 32 + 16));
            q3_0 = dot8(lA3, lB3, a, b);
        }

        float* plr = lr + (size_t)g * D * plane + (size_t)h * W_DIM + w0;
        int s = w0 - d0 + PAD;

#pragma unroll 4
        for (int i = 0; i < D; i++) {
            const int sc = max(s, 0);
            float4 a = *(const float4*)(r_raw + swz(sc * 32));
            float4 b = *(const float4*)(r_raw + swz(sc * 32 + 16));

            float c0 = dot8(lA0, lB0, a, b);
            float c1 = dot8(lA1, lB1, a, b);
            float c2 = dot8(lA2, lB2, a, b);
            float c3 = dot8(lA3, lB3, a, b);

            *(float4*)plr = make_float4(c0, q1, q2_0, q3_0);
            plr += plane;

            q1 = c1;
            q2_0 = q2_1; q2_1 = c2;
            q3_0 = q3_1; q3_1 = q3_2; q3_2 = c3;
            s -= 1;
        }
    } else {
        // ---- rl: fixed right quad (q0..q0+3); one l load per iter serves k=0..3
        // rl[q0+k, d0+i] = dot(l[q0+k+d0+i], r_k); load at iter j: l pos q0+d0+j+3
        // serves (k=3+j-i). Store row i: (c0(i-3), c1(i-2), c2(i-1), c3(i)).
        const int q0 = (tid - 64) * 4;
        float4 rA0 = *(const float4*)(r_raw + swz((q0 + 0 + PAD) * 32));
        float4 rB0 = *(const float4*)(r_raw + swz((q0 + 0 + PAD) * 32 + 16));
        float4 rA1 = *(const float4*)(r_raw + swz((q0 + 1 + PAD) * 32));
        float4 rB1 = *(const float4*)(r_raw + swz((q0 + 1 + PAD) * 32 + 16));
        float4 rA2 = *(const float4*)(r_raw + swz((q0 + 2 + PAD) * 32));
        float4 rB2 = *(const float4*)(r_raw + swz((q0 + 2 + PAD) * 32 + 16));
        float4 rA3 = *(const float4*)(r_raw + swz((q0 + 3 + PAD) * 32));
        float4 rB3 = *(const float4*)(r_raw + swz((q0 + 3 + PAD) * 32 + 16));

        // Prologue: loads at j=-3,-2,-1 (l positions q0+d0, q0+d0+1, q0+d0+2)
        float p0_0, p0_1, p0_2, p1_0, p1_1, p2_0;
        {
            int sl = q0 + d0;
            float4 a, b;
            a = *(const float4*)(l_raw + swz((sl + 0) * 32));
            b = *(const float4*)(l_raw + swz((sl + 0) * 32 + 16));
            p0_0 = dot8(a, b, rA0, rB0);
            a = *(const float4*)(l_raw + swz((sl + 1) * 32));
            b = *(const float4*)(l_raw + swz((sl + 1) * 32 + 16));
            p0_1 = dot8(a, b, rA0, rB0);
            p1_0 = dot8(a, b, rA1, rB1);
            a = *(const float4*)(l_raw + swz((sl + 2) * 32));
            b = *(const float4*)(l_raw + swz((sl + 2) * 32 + 16));
            p0_2 = dot8(a, b, rA0, rB0);
            p1_1 = dot8(a, b, rA1, rB1);
            p2_0 = dot8(a, b, rA2, rB2);
        }

        float* prl = rl + (size_t)g * D * plane + (size_t)h * W_DIM + q0;
        int s = q0 + d0 + 3;

#pragma unroll 4
        for (int i = 0; i < D; i++) {
            const int sc = min(s, SLOTS - 1);
            float4 a = *(const float4*)(l_raw + swz(sc * 32));
            float4 b = *(const float4*)(l_raw + swz(sc * 32 + 16));

            float c0 = dot8(a, b, rA0, rB0);
            float c1 = dot8(a, b, rA1, rB1);
            float c2 = dot8(a, b, rA2, rB2);
            float c3 = dot8(a, b, rA3, rB3);

            *(float4*)prl = make_float4(p0_0, p1_0, p2_0, c3);
            prl += plane;

            p0_0 = p0_1; p0_1 = p0_2; p0_2 = c0;
            p1_0 = p1_1; p1_1 = c1;
            p2_0 = c2;
            s += 1;
        }
    }
}

extern "C" void kernel_launch(void* const* d_in, const int* in_sizes, int n_in,
                              void* d_out, int out_size) {
    const float* L    = (const float*)d_in[0];
    const float* R    = (const float*)d_in[1];
    const int*   bins = (const int*)d_in[2];
    const int D = in_sizes[2];   // 48

    dim3 grid(H_DIM, G_DIM);     // one block per (h, g)
    dim3 block(128);             // 64 lr-quad threads + 64 rl-quad threads
    gwc_kernel<<<grid, block>>>(L, R, bins, D, (float*)d_out);
}

// round 11
// speedup vs baseline: 1.1709x; 1.0186x over previous
#include <cuda_runtime.h>
#include <cstdint>

// GwcVolume: B=1, F=320, H=128, W=256, G=40, C=8; D = in_sizes[2] (bins = arange(D))
#define W_DIM 256
#define H_DIM 128
#define G_DIM 40
#define C_DIM 8
#define PAD   48                 // max disparity padding (zeros)
#define SLOTS (W_DIM + PAD)      // 304 slots, 32B each (8 channels fp32)

// 128B XOR swizzle
__device__ __forceinline__ int swz(int off) {
    return off ^ ((off >> 3) & 0x70);
}

__device__ __forceinline__ float dot8(float4 la, float4 lb, float4 ra, float4 rb) {
    float s = la.x * ra.x;
    s = fmaf(la.y, ra.y, s);
    s = fmaf(la.z, ra.z, s);
    s = fmaf(la.w, ra.w, s);
    s = fmaf(lb.x, rb.x, s);
    s = fmaf(lb.y, rb.y, s);
    s = fmaf(lb.z, rb.z, s);
    s = fmaf(lb.w, rb.w, s);
    return s * 0.125f;           // mean over C=8
}

__global__ __launch_bounds__(128, 8)
void gwc_kernel(const float* __restrict__ L,
                const float* __restrict__ R,
                const int* __restrict__ bins,
                int D,
                float* __restrict__ out)
{
    __shared__ __align__(128) char l_raw[SLOTS * 32];  // slot p = left pos p    (zeros p>=256)
    __shared__ __align__(128) char r_raw[SLOTS * 32];  // slot p = right pos p-PAD (zeros p<PAD)
    __shared__ int d0_s;

    const int tid = threadIdx.x;
    const int h = blockIdx.x;
    const int g = blockIdx.y;

    if (tid == 0) d0_s = bins[0];

    const size_t plane = (size_t)H_DIM * W_DIM;
    const float* Lrow = L + (size_t)(g * C_DIM) * plane + (size_t)h * W_DIM;
    const float* Rrow = R + (size_t)(g * C_DIM) * plane + (size_t)h * W_DIM;

    // Populate left (transposed [w][c], swizzled), zero pad at top
    for (int p = tid; p < SLOTS; p += 128) {
        float v[8];
        if (p < W_DIM) {
#pragma unroll
            for (int c = 0; c < 8; c++) v[c] = Lrow[(size_t)c * plane + p];
        } else {
#pragma unroll
            for (int c = 0; c < 8; c++) v[c] = 0.0f;
        }
        *(float4*)(l_raw + swz(p * 32))      = make_float4(v[0], v[1], v[2], v[3]);
        *(float4*)(l_raw + swz(p * 32 + 16)) = make_float4(v[4], v[5], v[6], v[7]);
    }
    // Populate right, zero pad at bottom (PAD slots)
    for (int p = tid; p < SLOTS; p += 128) {
        float v[8];
        const int w = p - PAD;
        if (w >= 0) {
#pragma unroll
            for (int c = 0; c < 8; c++) v[c] = Rrow[(size_t)c * plane + w];
        } else {
#pragma unroll
            for (int c = 0; c < 8; c++) v[c] = 0.0f;
        }
        *(float4*)(r_raw + swz(p * 32))      = make_float4(v[0], v[1], v[2], v[3]);
        *(float4*)(r_raw + swz(p * 32 + 16)) = make_float4(v[4], v[5], v[6], v[7]);
    }
    __syncthreads();

    const int d0 = d0_s;
    const size_t VOL = (size_t)G_DIM * D * plane;
    float* __restrict__ lr = out;
    float* __restrict__ rl = out + VOL;

    if (tid < 64) {
        // ---- lr: fixed left quad (w0..w0+3); one r load per iter serves k=0..3
        // lr[w0+k, d0+i] = dot(l_k, r[w0+k-d0-i]); load at iter j: r pos w0-d0-j
        // serves (k, i=j+k). Store row i: (c0(i), c1(i-1), c2(i-2), c3(i-3)).
        const int w0 = tid * 4;
        float4 lA0 = *(const float4*)(l_raw + swz((w0 + 0) * 32));
        float4 lB0 = *(const float4*)(l_raw + swz((w0 + 0) * 32 + 16));
        float4 lA1 = *(const float4*)(l_raw + swz((w0 + 1) * 32));
        float4 lB1 = *(const float4*)(l_raw + swz((w0 + 1) * 32 + 16));
        float4 lA2 = *(const float4*)(l_raw + swz((w0 + 2) * 32));
        float4 lB2 = *(const float4*)(l_raw + swz((w0 + 2) * 32 + 16));
        float4 lA3 = *(const float4*)(l_raw + swz((w0 + 3) * 32));
        float4 lB3 = *(const float4*)(l_raw + swz((w0 + 3) * 32 + 16));

        // Prologue: loads at j=-1,-2,-3 (slots w0-d0+PAD+1..3, all < SLOTS)
        float q1, q2_0, q2_1, q3_0, q3_1, q3_2;
        {
            int sl = w0 - d0 + PAD;
            float4 a, b;
            a = *(const float4*)(r_raw + swz((sl + 1) * 32));
            b = *(const float4*)(r_raw + swz((sl + 1) * 32 + 16));
            q1   = dot8(lA1, lB1, a, b);
            q2_1 = dot8(lA2, lB2, a, b);
            q3_2 = dot8(lA3, lB3, a, b);
            a = *(const float4*)(r_raw + swz((sl + 2) * 32));
            b = *(const float4*)(r_raw + swz((sl + 2) * 32 + 16));
            q2_0 = dot8(lA2, lB2, a, b);
            q3_1 = dot8(lA3, lB3, a, b);
            a = *(const float4*)(r_raw + swz((sl + 3) * 32));
            b = *(const float4*)(r_raw + swz((sl + 3) * 32 + 16));
            q3_0 = dot8(lA3, lB3, a, b);
        }

        float* plr = lr + (size_t)g * D * plane + (size_t)h * W_DIM + w0;
        int s = w0 - d0 + PAD;

#pragma unroll 4
        for (int i = 0; i < D; i++) {
            const int sc = max(s, 0);
            float4 a = *(const float4*)(r_raw + swz(sc * 32));
            float4 b = *(const float4*)(r_raw + swz(sc * 32 + 16));

            float c0 = dot8(lA0, lB0, a, b);
            float c1 = dot8(lA1, lB1, a, b);
            float c2 = dot8(lA2, lB2, a, b);
            float c3 = dot8(lA3, lB3, a, b);

            *(float4*)plr = make_float4(c0, q1, q2_0, q3_0);
            plr += plane;

            q1 = c1;
            q2_0 = q2_1; q2_1 = c2;
            q3_0 = q3_1; q3_1 = q3_2; q3_2 = c3;
            s -= 1;
        }
    } else {
        // ---- rl: fixed right quad (q0..q0+3); one l load per iter serves k=0..3
        // rl[q0+k, d0+i] = dot(l[q0+k+d0+i], r_k); load at iter j: l pos q0+d0+j+3
        // serves (k=3+j-i). Store row i: (c0(i-3), c1(i-2), c2(i-1), c3(i)).
        const int q0 = (tid - 64) * 4;
        float4 rA0 = *(const float4*)(r_raw + swz((q0 + 0 + PAD) * 32));
        float4 rB0 = *(const float4*)(r_raw + swz((q0 + 0 + PAD) * 32 + 16));
        float4 rA1 = *(const float4*)(r_raw + swz((q0 + 1 + PAD) * 32));
        float4 rB1 = *(const float4*)(r_raw + swz((q0 + 1 + PAD) * 32 + 16));
        float4 rA2 = *(const float4*)(r_raw + swz((q0 + 2 + PAD) * 32));
        float4 rB2 = *(const float4*)(r_raw + swz((q0 + 2 + PAD) * 32 + 16));
        float4 rA3 = *(const float4*)(r_raw + swz((q0 + 3 + PAD) * 32));
        float4 rB3 = *(const float4*)(r_raw + swz((q0 + 3 + PAD) * 32 + 16));

        // Prologue: loads at j=-3,-2,-1 (l positions q0+d0, q0+d0+1, q0+d0+2)
        float p0_0, p0_1, p0_2, p1_0, p1_1, p2_0;
        {
            int sl = q0 + d0;
            float4 a, b;
            a = *(const float4*)(l_raw + swz((sl + 0) * 32));
            b = *(const float4*)(l_raw + swz((sl + 0) * 32 + 16));
            p0_0 = dot8(a, b, rA0, rB0);
            a = *(const float4*)(l_raw + swz((sl + 1) * 32));
            b = *(const float4*)(l_raw + swz((sl + 1) * 32 + 16));
            p0_1 = dot8(a, b, rA0, rB0);
            p1_0 = dot8(a, b, rA1, rB1);
            a = *(const float4*)(l_raw + swz((sl + 2) * 32));
            b = *(const float4*)(l_raw + swz((sl + 2) * 32 + 16));
            p0_2 = dot8(a, b, rA0, rB0);
            p1_1 = dot8(a, b, rA1, rB1);
            p2_0 = dot8(a, b, rA2, rB2);
        }

        float* prl = rl + (size_t)g * D * plane + (size_t)h * W_DIM + q0;
        int s = q0 + d0 + 3;

#pragma unroll 4
        for (int i = 0; i < D; i++) {
            const int sc = min(s, SLOTS - 1);
            float4 a = *(const float4*)(l_raw + swz(sc * 32));
            float4 b = *(const float4*)(l_raw + swz(sc * 32 + 16));

            float c0 = dot8(a, b, rA0, rB0);
            float c1 = dot8(a, b, rA1, rB1);
            float c2 = dot8(a, b, rA2, rB2);
            float c3 = dot8(a, b, rA3, rB3);

            *(float4*)prl = make_float4(p0_0, p1_0, p2_0, c3);
            prl += plane;

            p0_0 = p0_1; p0_1 = p0_2; p0_2 = c0;
            p1_0 = p1_1; p1_1 = c1;
            p2_0 = c2;
            s += 1;
        }
    }
}

extern "C" void kernel_launch(void* const* d_in, const int* in_sizes, int n_in,
                              void* d_out, int out_size) {
    const float* L    = (const float*)d_in[0];
    const float* R    = (const float*)d_in[1];
    const int*   bins = (const int*)d_in[2];
    const int D = in_sizes[2];   // 48

    dim3 grid(H_DIM, G_DIM);     // one block per (h, g)
    dim3 block(128);             // 64 lr-quad threads + 64 rl-quad threads
    gwc_kernel<<<grid, block>>>(L, R, bins, D, (float*)d_out);
}

// round 14
// speedup vs baseline: 1.1769x; 1.0051x over previous
#include <cuda_runtime.h>
#include <cstdint>

// GwcVolume: B=1, F=320, H=128, W=256, G=40, C=8; D = in_sizes[2] (bins = arange(D))
#define W_DIM 256
#define H_DIM 128
#define G_DIM 40
#define C_DIM 8
#define PAD   48                 // max disparity padding (zeros)
#define SLOTS (W_DIM + PAD)      // 304 slots, 32B each (8 channels fp32)

// 128B XOR swizzle
__device__ __forceinline__ int swz(int off) {
    return off ^ ((off >> 3) & 0x70);
}

__device__ __forceinline__ float dot8(float4 la, float4 lb, float4 ra, float4 rb) {
    float s = la.x * ra.x;
    s = fmaf(la.y, ra.y, s);
    s = fmaf(la.z, ra.z, s);
    s = fmaf(la.w, ra.w, s);
    s = fmaf(lb.x, rb.x, s);
    s = fmaf(lb.y, rb.y, s);
    s = fmaf(lb.z, rb.z, s);
    s = fmaf(lb.w, rb.w, s);
    return s * 0.125f;           // mean over C=8
}

__global__ __launch_bounds__(128, 8)
void gwc_kernel(const float* __restrict__ L,
                const float* __restrict__ R,
                const int* __restrict__ bins,
                int D,
                float* __restrict__ out)
{
    __shared__ __align__(128) char l_raw[SLOTS * 32];  // slot p = left pos p    (zeros p>=256)
    __shared__ __align__(128) char r_raw[SLOTS * 32];  // slot p = right pos p-PAD (zeros p<PAD)
    __shared__ int d0_s;

    const int tid = threadIdx.x;
    const int h = blockIdx.x;
    const int g = blockIdx.y;

    if (tid == 0) d0_s = bins[0];

    const size_t plane = (size_t)H_DIM * W_DIM;
    const float* Lrow = L + (size_t)(g * C_DIM) * plane + (size_t)h * W_DIM;
    const float* Rrow = R + (size_t)(g * C_DIM) * plane + (size_t)h * W_DIM;

    // Populate left (transposed [w][c], swizzled), zero pad at top
    for (int p = tid; p < SLOTS; p += 128) {
        float v[8];
        if (p < W_DIM) {
#pragma unroll
            for (int c = 0; c < 8; c++) v[c] = Lrow[(size_t)c * plane + p];
        } else {
#pragma unroll
            for (int c = 0; c < 8; c++) v[c] = 0.0f;
        }
        *(float4*)(l_raw + swz(p * 32))      = make_float4(v[0], v[1], v[2], v[3]);
        *(float4*)(l_raw + swz(p * 32 + 16)) = make_float4(v[4], v[5], v[6], v[7]);
    }
    // Populate right, zero pad at bottom (PAD slots)
    for (int p = tid; p < SLOTS; p += 128) {
        float v[8];
        const int w = p - PAD;
        if (w >= 0) {
#pragma unroll
            for (int c = 0; c < 8; c++) v[c] = Rrow[(size_t)c * plane + w];
        } else {
#pragma unroll
            for (int c = 0; c < 8; c++) v[c] = 0.0f;
        }
        *(float4*)(r_raw + swz(p * 32))      = make_float4(v[0], v[1], v[2], v[3]);
        *(float4*)(r_raw + swz(p * 32 + 16)) = make_float4(v[4], v[5], v[6], v[7]);
    }
    __syncthreads();

    const int d0 = d0_s;
    const size_t VOL = (size_t)G_DIM * D * plane;
    float* __restrict__ lr = out;
    float* __restrict__ rl = out + VOL;

    if (tid < 64) {
        // ---- lr: fixed left quad (w0..w0+3); one r load per iter serves k=0..3
        // lr[w0+k, d0+i] = dot(l_k, r[w0+k-d0-i]); load at iter j: r pos w0-d0-j
        // serves (k, i=j+k). Store row i: (c0(i), c1(i-1), c2(i-2), c3(i-3)).
        const int w0 = tid * 4;
        float4 lA0 = *(const float4*)(l_raw + swz((w0 + 0) * 32));
        float4 lB0 = *(const float4*)(l_raw + swz((w0 + 0) * 32 + 16));
        float4 lA1 = *(const float4*)(l_raw + swz((w0 + 1) * 32));
        float4 lB1 = *(const float4*)(l_raw + swz((w0 + 1) * 32 + 16));
        float4 lA2 = *(const float4*)(l_raw + swz((w0 + 2) * 32));
        float4 lB2 = *(const float4*)(l_raw + swz((w0 + 2) * 32 + 16));
        float4 lA3 = *(const float4*)(l_raw + swz((w0 + 3) * 32));
        float4 lB3 = *(const float4*)(l_raw + swz((w0 + 3) * 32 + 16));

        // Prologue: loads at j=-1,-2,-3 (slots w0-d0+PAD+1..3, all < SLOTS)
        float q1, q2_0, q2_1, q3_0, q3_1, q3_2;
        {
            int sl = w0 - d0 + PAD;
            float4 a, b;
            a = *(const float4*)(r_raw + swz((sl + 1) * 32));
            b = *(const float4*)(r_raw + swz((sl + 1) * 32 + 16));
            q1   = dot8(lA1, lB1, a, b);
            q2_1 = dot8(lA2, lB2, a, b);
            q3_2 = dot8(lA3, lB3, a, b);
            a = *(const float4*)(r_raw + swz((sl + 2) * 32));
            b = *(const float4*)(r_raw + swz((sl + 2) * 32 + 16));
            q2_0 = dot8(lA2, lB2, a, b);
            q3_1 = dot8(lA3, lB3, a, b);
            a = *(const float4*)(r_raw + swz((sl + 3) * 32));
            b = *(const float4*)(r_raw + swz((sl + 3) * 32 + 16));
            q3_0 = dot8(lA3, lB3, a, b);
        }

        float* plr = lr + (size_t)g * D * plane + (size_t)h * W_DIM + w0;
        int s = w0 - d0 + PAD;

#pragma unroll 4
        for (int i = 0; i < D; i++) {
            const int sc = max(s, 0);
            float4 a = *(const float4*)(r_raw + swz(sc * 32));
            float4 b = *(const float4*)(r_raw + swz(sc * 32 + 16));

            float c0 = dot8(lA0, lB0, a, b);
            float c1 = dot8(lA1, lB1, a, b);
            float c2 = dot8(lA2, lB2, a, b);
            float c3 = dot8(lA3, lB3, a, b);

            *(float4*)plr = make_float4(c0, q1, q2_0, q3_0);
            plr += plane;

            q1 = c1;
            q2_0 = q2_1; q2_1 = c2;
            q3_0 = q3_1; q3_1 = q3_2; q3_2 = c3;
            s -= 1;
        }
    } else {
        // ---- rl: fixed right quad (q0..q0+3); one l load per iter serves k=0..3
        // rl[q0+k, d0+i] = dot(l[q0+k+d0+i], r_k); load at iter j: l pos q0+d0+j+3
        // serves (k=3+j-i). Store row i: (c0(i-3), c1(i-2), c2(i-1), c3(i)).
        const int q0 = (tid - 64) * 4;
        float4 rA0 = *(const float4*)(r_raw + swz((q0 + 0 + PAD) * 32));
        float4 rB0 = *(const float4*)(r_raw + swz((q0 + 0 + PAD) * 32 + 16));
        float4 rA1 = *(const float4*)(r_raw + swz((q0 + 1 + PAD) * 32));
        float4 rB1 = *(const float4*)(r_raw + swz((q0 + 1 + PAD) * 32 + 16));
        float4 rA2 = *(const float4*)(r_raw + swz((q0 + 2 + PAD) * 32));
        float4 rB2 = *(const float4*)(r_raw + swz((q0 + 2 + PAD) * 32 + 16));
        float4 rA3 = *(const float4*)(r_raw + swz((q0 + 3 + PAD) * 32));
        float4 rB3 = *(const float4*)(r_raw + swz((q0 + 3 + PAD) * 32 + 16));

        // Prologue: loads at j=-3,-2,-1 (l positions q0+d0, q0+d0+1, q0+d0+2)
        float p0_0, p0_1, p0_2, p1_0, p1_1, p2_0;
        {
            int sl = q0 + d0;
            float4 a, b;
            a = *(const float4*)(l_raw + swz((sl + 0) * 32));
            b = *(const float4*)(l_raw + swz((sl + 0) * 32 + 16));
            p0_0 = dot8(a, b, rA0, rB0);
            a = *(const float4*)(l_raw + swz((sl + 1) * 32));
            b = *(const float4*)(l_raw + swz((sl + 1) * 32 + 16));
            p0_1 = dot8(a, b, rA0, rB0);
            p1_0 = dot8(a, b, rA1, rB1);
            a = *(const float4*)(l_raw + swz((sl + 2) * 32));
            b = *(const float4*)(l_raw + swz((sl + 2) * 32 + 16));
            p0_2 = dot8(a, b, rA0, rB0);
            p1_1 = dot8(a, b, rA1, rB1);
            p2_0 = dot8(a, b, rA2, rB2);
        }

        float* prl = rl + (size_t)g * D * plane + (size_t)h * W_DIM + q0;
        int s = q0 + d0 + 3;

#pragma unroll 4
        for (int i = 0; i < D; i++) {
            const int sc = min(s, SLOTS - 1);
            float4 a = *(const float4*)(l_raw + swz(sc * 32));
            float4 b = *(const float4*)(l_raw + swz(sc * 32 + 16));

            float c0 = dot8(a, b, rA0, rB0);
            float c1 = dot8(a, b, rA1, rB1);
            float c2 = dot8(a, b, rA2, rB2);
            float c3 = dot8(a, b, rA3, rB3);

            *(float4*)prl = make_float4(p0_0, p1_0, p2_0, c3);
            prl += plane;

            p0_0 = p0_1; p0_1 = p0_2; p0_2 = c0;
            p1_0 = p1_1; p1_1 = c1;
            p2_0 = c2;
            s += 1;
        }
    }
}

extern "C" void kernel_launch(void* const* d_in, const int* in_sizes, int n_in,
                              void* d_out, int out_size) {
    const float* L    = (const float*)d_in[0];
    const float* R    = (const float*)d_in[1];
    const int*   bins = (const int*)d_in[2];
    const int D = in_sizes[2];   // 48

    dim3 grid(H_DIM, G_DIM);     // one block per (h, g)
    dim3 block(128);             // 64 lr-quad threads + 64 rl-quad threads
    gwc_kernel<<<grid, block>>>(L, R, bins, D, (float*)d_out);
}